// round 1
// baseline (speedup 1.0000x reference)
#include <cuda_runtime.h>
#include <math.h>

// Problem constants
#define LL 2048
#define SS 2048
#define NB 2
#define HH 16
#define DD 64
#define EE 1024
#define BH 32          // NB*HH
#define MROWS 4096     // LL*NB

// Scratch: head-major projected tensors [bh][t][d], bh = n*16 + h
__device__ float g_q[(size_t)BH * LL * DD];
__device__ float g_k[(size_t)BH * SS * DD];
__device__ float g_v[(size_t)BH * SS * DD];
__device__ float g_o[(size_t)BH * LL * DD];

// ---------------------------------------------------------------------------
// Projection GEMM: dst_heads = X(4096x1024) @ W(1024x1024), output head-major.
// Block tile 64x64, K-chunk 32, 256 threads, 4x4 per thread.
// ---------------------------------------------------------------------------
__global__ __launch_bounds__(256) void proj_kernel(const float* __restrict__ X,
                                                   const float* __restrict__ W,
                                                   float* __restrict__ dst)
{
    __shared__ float As[32][68];   // [k][m]
    __shared__ float Bs[32][68];   // [k][n]
    const int tid = threadIdx.x;
    const int ty = tid >> 4;
    const int tx = tid & 15;
    const int m0 = blockIdx.y * 64;
    const int n0 = blockIdx.x * 64;

    float acc[4][4];
#pragma unroll
    for (int i = 0; i < 4; i++)
#pragma unroll
        for (int j = 0; j < 4; j++) acc[i][j] = 0.f;

    const int alr = tid >> 3;          // 0..31
    const int alc = (tid & 7) * 4;     // 0..28
    const int blr = tid >> 4;          // 0..15
    const int blc = (tid & 15) * 4;    // 0..60

    for (int k0 = 0; k0 < EE; k0 += 32) {
#pragma unroll
        for (int p = 0; p < 2; p++) {
            int r = alr + p * 32;
            float4 v = *(const float4*)&X[(size_t)(m0 + r) * EE + k0 + alc];
            As[alc + 0][r] = v.x;
            As[alc + 1][r] = v.y;
            As[alc + 2][r] = v.z;
            As[alc + 3][r] = v.w;
        }
#pragma unroll
        for (int p = 0; p < 2; p++) {
            int kk = blr + p * 16;
            *(float4*)&Bs[kk][blc] =
                *(const float4*)&W[(size_t)(k0 + kk) * EE + n0 + blc];
        }
        __syncthreads();
#pragma unroll
        for (int kk = 0; kk < 32; kk++) {
            float4 a = *(const float4*)&As[kk][ty * 4];
            float4 b = *(const float4*)&Bs[kk][tx * 4];
            float av[4] = {a.x, a.y, a.z, a.w};
            float bv[4] = {b.x, b.y, b.z, b.w};
#pragma unroll
            for (int i = 0; i < 4; i++)
#pragma unroll
                for (int j = 0; j < 4; j++)
                    acc[i][j] = fmaf(av[i], bv[j], acc[i][j]);
        }
        __syncthreads();
    }

    const int h = n0 >> 6;       // n0 is a multiple of 64
    const int d = tx * 4;
#pragma unroll
    for (int ii = 0; ii < 4; ii++) {
        int r = m0 + ty * 4 + ii;
        int t = r >> 1;
        int n = r & 1;
        int bh = n * 16 + h;
        float4 v = make_float4(acc[ii][0], acc[ii][1], acc[ii][2], acc[ii][3]);
        *(float4*)&dst[((size_t)(bh * LL + t)) * DD + d] = v;
    }
}

// ---------------------------------------------------------------------------
// Output projection: out = heads(g_o) reassembled (4096x1024) @ Wo(1024x1024)
// ---------------------------------------------------------------------------
__global__ __launch_bounds__(256) void outproj_kernel(const float* __restrict__ W,
                                                      float* __restrict__ out)
{
    __shared__ float As[32][68];
    __shared__ float Bs[32][68];
    const int tid = threadIdx.x;
    const int ty = tid >> 4;
    const int tx = tid & 15;
    const int m0 = blockIdx.y * 64;
    const int n0 = blockIdx.x * 64;

    float acc[4][4];
#pragma unroll
    for (int i = 0; i < 4; i++)
#pragma unroll
        for (int j = 0; j < 4; j++) acc[i][j] = 0.f;

    const int alr = tid >> 3;
    const int alc = (tid & 7) * 4;
    const int blr = tid >> 4;
    const int blc = (tid & 15) * 4;

    for (int k0 = 0; k0 < EE; k0 += 32) {
        const int h = k0 >> 6;
        const int db = (k0 & 63) + alc;
#pragma unroll
        for (int p = 0; p < 2; p++) {
            int r = alr + p * 32;
            int gr = m0 + r;
            int t = gr >> 1;
            int n = gr & 1;
            float4 v = *(const float4*)&g_o[((size_t)((n * 16 + h) * LL + t)) * DD + db];
            As[alc + 0][r] = v.x;
            As[alc + 1][r] = v.y;
            As[alc + 2][r] = v.z;
            As[alc + 3][r] = v.w;
        }
#pragma unroll
        for (int p = 0; p < 2; p++) {
            int kk = blr + p * 16;
            *(float4*)&Bs[kk][blc] =
                *(const float4*)&W[(size_t)(k0 + kk) * EE + n0 + blc];
        }
        __syncthreads();
#pragma unroll
        for (int kk = 0; kk < 32; kk++) {
            float4 a = *(const float4*)&As[kk][ty * 4];
            float4 b = *(const float4*)&Bs[kk][tx * 4];
            float av[4] = {a.x, a.y, a.z, a.w};
            float bv[4] = {b.x, b.y, b.z, b.w};
#pragma unroll
            for (int i = 0; i < 4; i++)
#pragma unroll
                for (int j = 0; j < 4; j++)
                    acc[i][j] = fmaf(av[i], bv[j], acc[i][j]);
        }
        __syncthreads();
    }

#pragma unroll
    for (int ii = 0; ii < 4; ii++) {
        int r = m0 + ty * 4 + ii;
        float4 v = make_float4(acc[ii][0], acc[ii][1], acc[ii][2], acc[ii][3]);
        *(float4*)&out[(size_t)r * EE + n0 + tx * 4] = v;
    }
}

// ---------------------------------------------------------------------------
// Flash-style attention per (head, 64-row L tile). Fuses:
//  logits = (Q K^T)/8 + prev, masks, logits-write, online softmax, P@V.
// ---------------------------------------------------------------------------
#define SMEM_ATTN (4 * 64 * 68 * 4)

__global__ __launch_bounds__(256) void attn_kernel(const float* __restrict__ prev,
                                                   const unsigned char* __restrict__ attn_mask,
                                                   const unsigned char* __restrict__ kpm,
                                                   float* __restrict__ out_logits)
{
    extern __shared__ float smattn[];
    float (*Qs)[68] = (float(*)[68])smattn;                 // [d][i]
    float (*Ks)[68] = (float(*)[68])(smattn + 64 * 68);     // [d][j]
    float (*Vs)[68] = (float(*)[68])(smattn + 2 * 64 * 68); // [j][d]
    float (*Ps)[68] = (float(*)[68])(smattn + 3 * 64 * 68); // [j][i]

    const int tid = threadIdx.x;
    const int ty = tid >> 4;
    const int tx = tid & 15;
    const int bh = blockIdx.y;
    const int n = bh >> 4;
    const int r0 = blockIdx.x * 64;

    const int li = tid >> 4;          // loader row 0..15
    const int dc = (tid & 15) * 4;    // loader col 0..60

    // Load Q tile (transposed into [d][i])
#pragma unroll
    for (int p = 0; p < 4; p++) {
        int i = li + p * 16;
        float4 v = *(const float4*)&g_q[((size_t)(bh * LL + r0 + i)) * DD + dc];
        Qs[dc + 0][i] = v.x;
        Qs[dc + 1][i] = v.y;
        Qs[dc + 2][i] = v.z;
        Qs[dc + 3][i] = v.w;
    }

    float o[4][4];
    float mrow[4], lrow[4];
#pragma unroll
    for (int i = 0; i < 4; i++) {
        mrow[i] = -INFINITY;
        lrow[i] = 0.f;
#pragma unroll
        for (int j = 0; j < 4; j++) o[i][j] = 0.f;
    }

    for (int s0 = 0; s0 < SS; s0 += 64) {
        __syncthreads();  // previous P@V done before overwriting K/V/Ps
#pragma unroll
        for (int p = 0; p < 4; p++) {
            int j = li + p * 16;
            float4 kv = *(const float4*)&g_k[((size_t)(bh * SS + s0 + j)) * DD + dc];
            Ks[dc + 0][j] = kv.x;
            Ks[dc + 1][j] = kv.y;
            Ks[dc + 2][j] = kv.z;
            Ks[dc + 3][j] = kv.w;
            float4 vv = *(const float4*)&g_v[((size_t)(bh * SS + s0 + j)) * DD + dc];
            *(float4*)&Vs[j][dc] = vv;
        }
        __syncthreads();

        // S = Q K^T
        float acc[4][4];
#pragma unroll
        for (int i = 0; i < 4; i++)
#pragma unroll
            for (int j = 0; j < 4; j++) acc[i][j] = 0.f;
#pragma unroll
        for (int d = 0; d < 64; d++) {
            float4 a = *(const float4*)&Qs[d][ty * 4];
            float4 b = *(const float4*)&Ks[d][tx * 4];
            float av[4] = {a.x, a.y, a.z, a.w};
            float bv[4] = {b.x, b.y, b.z, b.w};
#pragma unroll
            for (int i = 0; i < 4; i++)
#pragma unroll
                for (int j = 0; j < 4; j++)
                    acc[i][j] = fmaf(av[i], bv[j], acc[i][j]);
        }

        // logits + masks + logits write + online softmax stats + P into smem
        float sc[4];
#pragma unroll
        for (int ii = 0; ii < 4; ii++) {
            int row = r0 + ty * 4 + ii;
            size_t base = ((size_t)bh * LL + row) * SS + s0 + tx * 4;
            float4 pv = *(const float4*)&prev[base];
            const unsigned char* amp = &attn_mask[(size_t)row * SS + s0 + tx * 4];
            const unsigned char* kmp = &kpm[(size_t)n * SS + s0 + tx * 4];
            float lg[4];
            float pvv[4] = {pv.x, pv.y, pv.z, pv.w};
#pragma unroll
            for (int jj = 0; jj < 4; jj++) {
                bool msk = (amp[jj] != 0) || (kmp[jj] != 0);
                lg[jj] = msk ? -INFINITY : fmaf(acc[ii][jj], 0.125f, pvv[jj]);
            }
            *(float4*)&out_logits[base] = make_float4(lg[0], lg[1], lg[2], lg[3]);

            float tmax = fmaxf(fmaxf(lg[0], lg[1]), fmaxf(lg[2], lg[3]));
#pragma unroll
            for (int off = 8; off > 0; off >>= 1)
                tmax = fmaxf(tmax, __shfl_xor_sync(0xffffffffu, tmax, off));
            float mnew = fmaxf(mrow[ii], tmax);
            float scl = (mnew == -INFINITY) ? 1.f : expf(mrow[ii] - mnew);
            float psum = 0.f;
            float pj[4];
#pragma unroll
            for (int jj = 0; jj < 4; jj++) {
                float p = (mnew == -INFINITY) ? 0.f : expf(lg[jj] - mnew);
                pj[jj] = p;
                psum += p;
            }
#pragma unroll
            for (int off = 8; off > 0; off >>= 1)
                psum += __shfl_xor_sync(0xffffffffu, psum, off);
            lrow[ii] = lrow[ii] * scl + psum;
            mrow[ii] = mnew;
            sc[ii] = scl;
#pragma unroll
            for (int jj = 0; jj < 4; jj++)
                Ps[tx * 4 + jj][ty * 4 + ii] = pj[jj];
        }
        __syncthreads();

        // O = O*scale + P @ V
#pragma unroll
        for (int ii = 0; ii < 4; ii++)
#pragma unroll
            for (int dd = 0; dd < 4; dd++) o[ii][dd] *= sc[ii];
#pragma unroll
        for (int j = 0; j < 64; j++) {
            float4 a = *(const float4*)&Ps[j][ty * 4];
            float4 b = *(const float4*)&Vs[j][tx * 4];
            float av[4] = {a.x, a.y, a.z, a.w};
            float bv[4] = {b.x, b.y, b.z, b.w};
#pragma unroll
            for (int ii = 0; ii < 4; ii++)
#pragma unroll
                for (int dd = 0; dd < 4; dd++)
                    o[ii][dd] = fmaf(av[ii], bv[dd], o[ii][dd]);
        }
    }

#pragma unroll
    for (int ii = 0; ii < 4; ii++) {
        float inv = 1.f / lrow[ii];
        int row = r0 + ty * 4 + ii;
        float4 v = make_float4(o[ii][0] * inv, o[ii][1] * inv,
                               o[ii][2] * inv, o[ii][3] * inv);
        *(float4*)&g_o[((size_t)(bh * LL + row)) * DD + tx * 4] = v;
    }
}

// ---------------------------------------------------------------------------
extern "C" void kernel_launch(void* const* d_in, const int* in_sizes, int n_in,
                              void* d_out, int out_size)
{
    const float* query = (const float*)d_in[0];
    const float* key   = (const float*)d_in[1];
    const float* value = (const float*)d_in[2];
    const float* prev  = (const float*)d_in[3];
    const unsigned char* kpm = (const unsigned char*)d_in[4];
    const unsigned char* am  = (const unsigned char*)d_in[5];
    const float* Wq = (const float*)d_in[6];
    const float* Wk = (const float*)d_in[7];
    const float* Wv = (const float*)d_in[8];
    const float* Wo = (const float*)d_in[9];

    float* out = (float*)d_out;
    float* out_logits = out + (size_t)LL * NB * EE;   // tuple: (out, attn_logits)

    float *gq, *gk, *gv;
    cudaGetSymbolAddress((void**)&gq, g_q);
    cudaGetSymbolAddress((void**)&gk, g_k);
    cudaGetSymbolAddress((void**)&gv, g_v);

    cudaFuncSetAttribute(attn_kernel,
                         cudaFuncAttributeMaxDynamicSharedMemorySize, SMEM_ATTN);

    dim3 gproj(EE / 64, MROWS / 64);
    proj_kernel<<<gproj, 256>>>(query, Wq, gq);
    proj_kernel<<<gproj, 256>>>(key,   Wk, gk);
    proj_kernel<<<gproj, 256>>>(value, Wv, gv);
    attn_kernel<<<dim3(LL / 64, BH), 256, SMEM_ATTN>>>(prev, am, kpm, out_logits);
    outproj_kernel<<<gproj, 256>>>(Wo, out);
}

// round 4
// speedup vs baseline: 1.3581x; 1.3581x over previous
#include <cuda_runtime.h>
#include <cuda_bf16.h>
#include <math.h>
#include <stdint.h>

// Problem constants
#define LL 2048
#define SS 2048
#define NB 2
#define HH 16
#define DD 64
#define EE 1024
#define BH 32          // NB*HH
#define MROWS 4096     // LL*NB

// ---------------------------------------------------------------------------
// Scratch (device globals; no allocation allowed)
// ---------------------------------------------------------------------------
__device__ float g_q[(size_t)BH * LL * DD];
__device__ float g_k[(size_t)BH * SS * DD];
__device__ float g_v[(size_t)BH * SS * DD];
__device__ float g_o[(size_t)BH * LL * DD];

__device__ __nv_bfloat16 g_ah[(size_t)MROWS * EE];
__device__ __nv_bfloat16 g_al[(size_t)MROWS * EE];
__device__ __nv_bfloat16 g_bh[(size_t)EE * EE];
__device__ __nv_bfloat16 g_bl[(size_t)EE * EE];

// ---------------------------------------------------------------------------
// mma.sync GEMM: C[4096x1024] = X*W via bf16x3 split (K' = 3*1024)
// A term sources: [Xh | Xl | Xh], B: [Wh | Wh | Wl] (B given transposed [n][k])
// CTA tile 128x128, 8 warps (2m x 4n), warp tile 64x32, 3-stage cp.async.
// ---------------------------------------------------------------------------
#define NSTAGE 3
#define KSTEP 64
#define NIT 48                       // 3072 / 64
#define STAGE_BYTES 32768            // A 16KB + B 16KB
#define AOFF 0
#define BOFF 16384
#define GSM_TOTAL (NSTAGE * STAGE_BYTES)

__device__ __forceinline__ uint32_t smem_u32(const void* p) {
    uint32_t a;
    asm("{ .reg .u64 t; cvta.to.shared.u64 t, %1; cvt.u32.u64 %0, t; }"
        : "=r"(a) : "l"(p));
    return a;
}

__device__ __forceinline__ void ldmatrix4(uint32_t* r, uint32_t addr) {
    asm volatile("ldmatrix.sync.aligned.m8n8.x4.shared.b16 {%0,%1,%2,%3}, [%4];"
                 : "=r"(r[0]), "=r"(r[1]), "=r"(r[2]), "=r"(r[3]) : "r"(addr));
}

__device__ __forceinline__ void mma16816(float* c, const uint32_t* a,
                                         uint32_t b0, uint32_t b1) {
    asm volatile("mma.sync.aligned.m16n8k16.row.col.f32.bf16.bf16.f32 "
                 "{%0,%1,%2,%3}, {%4,%5,%6,%7}, {%8,%9}, {%0,%1,%2,%3};"
                 : "+f"(c[0]), "+f"(c[1]), "+f"(c[2]), "+f"(c[3])
                 : "r"(a[0]), "r"(a[1]), "r"(a[2]), "r"(a[3]), "r"(b0), "r"(b1));
}

__device__ __forceinline__ void load_tile(int it, int buf, int tid, int m0, int n0,
                                          const __nv_bfloat16* __restrict__ Ah,
                                          const __nv_bfloat16* __restrict__ Al,
                                          const __nv_bfloat16* __restrict__ Bth,
                                          const __nv_bfloat16* __restrict__ Btl,
                                          uint32_t sb)
{
    const int term = it >> 4;                    // 0,1,2
    const int kc = (it & 15) << 6;               // k offset within 1024
    const __nv_bfloat16* As = (term == 1) ? Al : Ah;
    const __nv_bfloat16* Bs = (term == 2) ? Btl : Bth;
    const uint32_t abase = sb + buf * STAGE_BYTES + AOFF;
    const uint32_t bbase = sb + buf * STAGE_BYTES + BOFF;
#pragma unroll
    for (int i = 0; i < 8; i++) {
        int g = i * 256 + tid;                   // 0..2047 chunks of 16B
        int row = (g >> 3) & 127;
        int c = g & 7;
        const __nv_bfloat16* src;
        uint32_t dst;
        if (g < 1024) {
            src = As + (size_t)(m0 + row) * EE + kc + (c << 3);
            dst = abase + row * 128 + ((c ^ (row & 7)) << 4);
        } else {
            src = Bs + (size_t)(n0 + row) * EE + kc + (c << 3);
            dst = bbase + row * 128 + ((c ^ (row & 7)) << 4);
        }
        asm volatile("cp.async.cg.shared.global [%0], [%1], 16;"
                     :: "r"(dst), "l"(src));
    }
}

__global__ void __launch_bounds__(256, 1) gemm_mma_bf16x3(
    const __nv_bfloat16* __restrict__ Ah, const __nv_bfloat16* __restrict__ Al,
    const __nv_bfloat16* __restrict__ Bth, const __nv_bfloat16* __restrict__ Btl,
    float* __restrict__ dst, int headmode)
{
    extern __shared__ __align__(1024) char sm[];
    const uint32_t sb = smem_u32(sm);
    const int tid = threadIdx.x;
    const int wid = tid >> 5, lane = tid & 31;
    const int wm = wid >> 2;           // 0..1
    const int wn = wid & 3;            // 0..3
    const int m0 = blockIdx.y * 128;
    const int n0 = blockIdx.x * 128;

    float acc[4][4][4];
#pragma unroll
    for (int i = 0; i < 4; i++)
#pragma unroll
        for (int j = 0; j < 4; j++)
#pragma unroll
            for (int k = 0; k < 4; k++) acc[i][j][k] = 0.f;

    // Prologue: stages 0,1
    load_tile(0, 0, tid, m0, n0, Ah, Al, Bth, Btl, sb);
    asm volatile("cp.async.commit_group;" ::: "memory");
    load_tile(1, 1, tid, m0, n0, Ah, Al, Bth, Btl, sb);
    asm volatile("cp.async.commit_group;" ::: "memory");

    // Precompute ldmatrix lane addressing
    const int a_r = (lane & 7) + ((lane >> 3) & 1) * 8;   // row within 16
    const int a_c8 = lane >> 4;                           // k-half (0/1)
    const int b_r = (lane & 7) + (lane >> 4) * 8;         // n within 16
    const int b_c8 = (lane >> 3) & 1;                     // k-half

    for (int it = 0; it < NIT; ++it) {
        asm volatile("cp.async.wait_group 1;" ::: "memory");
        __syncthreads();
        if (it + 2 < NIT)
            load_tile(it + 2, (it + 2) % NSTAGE, tid, m0, n0, Ah, Al, Bth, Btl, sb);
        asm volatile("cp.async.commit_group;" ::: "memory");

        const int buf = it % NSTAGE;
        const uint32_t Ab = sb + buf * STAGE_BYTES + AOFF;
        const uint32_t Bb = sb + buf * STAGE_BYTES + BOFF;
#pragma unroll
        for (int ks = 0; ks < 4; ks++) {
            const int k0 = ks * 16;
            uint32_t a[4][4];
#pragma unroll
            for (int mt = 0; mt < 4; mt++) {
                int row = wm * 64 + mt * 16 + a_r;
                int col = k0 + 8 * a_c8;
                uint32_t addr = Ab + row * 128 + (((col >> 3) ^ (row & 7)) << 4);
                ldmatrix4(a[mt], addr);
            }
            uint32_t b[2][4];
#pragma unroll
            for (int bt = 0; bt < 2; bt++) {
                int row = wn * 32 + bt * 16 + b_r;
                int col = k0 + 8 * b_c8;
                uint32_t addr = Bb + row * 128 + (((col >> 3) ^ (row & 7)) << 4);
                ldmatrix4(b[bt], addr);
            }
#pragma unroll
            for (int mt = 0; mt < 4; mt++) {
#pragma unroll
                for (int nt = 0; nt < 4; nt++) {
                    uint32_t b0 = b[nt >> 1][(nt & 1) * 2];
                    uint32_t b1 = b[nt >> 1][(nt & 1) * 2 + 1];
                    mma16816(acc[mt][nt], a[mt], b0, b1);
                }
            }
        }
    }

    // Epilogue
#pragma unroll
    for (int mt = 0; mt < 4; mt++) {
#pragma unroll
        for (int nt = 0; nt < 4; nt++) {
            int m = m0 + wm * 64 + mt * 16 + (lane >> 2);
            int n = n0 + wn * 32 + nt * 8 + 2 * (lane & 3);
#pragma unroll
            for (int half = 0; half < 2; half++) {
                int mm = m + half * 8;
                float2 v = make_float2(acc[mt][nt][half * 2],
                                       acc[mt][nt][half * 2 + 1]);
                if (headmode) {
                    int t = mm >> 1, nb = mm & 1;
                    int h = n >> 6, d = n & 63;
                    *(float2*)&dst[((size_t)((nb * HH + h) * LL + t)) * DD + d] = v;
                } else {
                    *(float2*)&dst[(size_t)mm * EE + n] = v;
                }
            }
        }
    }
}

// ---------------------------------------------------------------------------
// Conversion kernels
// ---------------------------------------------------------------------------
__global__ void __launch_bounds__(256) split_kernel(const float* __restrict__ x,
                                                    __nv_bfloat16* __restrict__ h,
                                                    __nv_bfloat16* __restrict__ l,
                                                    int n4)
{
    int i = blockIdx.x * 256 + threadIdx.x;
    if (i >= n4) return;
    float4 v = ((const float4*)x)[i];
    float vv[4] = {v.x, v.y, v.z, v.w};
    __nv_bfloat162 hh[2], ll[2];
#pragma unroll
    for (int j = 0; j < 2; j++) {
        __nv_bfloat16 h0 = __float2bfloat16(vv[2 * j]);
        __nv_bfloat16 h1 = __float2bfloat16(vv[2 * j + 1]);
        __nv_bfloat16 l0 = __float2bfloat16(vv[2 * j] - __bfloat162float(h0));
        __nv_bfloat16 l1 = __float2bfloat16(vv[2 * j + 1] - __bfloat162float(h1));
        hh[j] = __nv_bfloat162(h0, h1);
        ll[j] = __nv_bfloat162(l0, l1);
    }
    *(__nv_bfloat162*)(h + 4 * (size_t)i)     = hh[0];
    *(__nv_bfloat162*)(h + 4 * (size_t)i + 2) = hh[1];
    *(__nv_bfloat162*)(l + 4 * (size_t)i)     = ll[0];
    *(__nv_bfloat162*)(l + 4 * (size_t)i + 2) = ll[1];
}

// W[k][n] -> Wt[n][k] bf16 hi/lo
__global__ void __launch_bounds__(256) wtrans_split(const float* __restrict__ W,
                                                    __nv_bfloat16* __restrict__ th,
                                                    __nv_bfloat16* __restrict__ tl)
{
    __shared__ float t[32][33];
    const int n0 = blockIdx.x * 32, k0 = blockIdx.y * 32;
    const int tx = threadIdx.x & 31, ty = threadIdx.x >> 5;
#pragma unroll
    for (int j = 0; j < 32; j += 8)
        t[ty + j][tx] = W[(size_t)(k0 + ty + j) * EE + n0 + tx];
    __syncthreads();
#pragma unroll
    for (int j = 0; j < 32; j += 8) {
        float v = t[tx][ty + j];
        __nv_bfloat16 h = __float2bfloat16(v);
        __nv_bfloat16 l = __float2bfloat16(v - __bfloat162float(h));
        th[(size_t)(n0 + ty + j) * EE + k0 + tx] = h;
        tl[(size_t)(n0 + ty + j) * EE + k0 + tx] = l;
    }
}

// head-major g_o -> row-major [r][E] bf16 hi/lo
__global__ void __launch_bounds__(256) osplit_kernel(const float* __restrict__ go,
                                                     __nv_bfloat16* __restrict__ h,
                                                     __nv_bfloat16* __restrict__ l)
{
    int i = blockIdx.x * 256 + threadIdx.x;     // over MROWS*EE/4
    if (i >= MROWS * EE / 4) return;
    int e = (i << 2) & (EE - 1);
    int r = (i << 2) >> 10;
    int hh_ = e >> 6, d0 = e & 63, t = r >> 1, nn = r & 1;
    float4 v = *(const float4*)&go[((size_t)((nn * HH + hh_) * LL + t)) * DD + d0];
    float vv[4] = {v.x, v.y, v.z, v.w};
    size_t base = (size_t)r * EE + e;
#pragma unroll
    for (int j = 0; j < 4; j++) {
        __nv_bfloat16 hb = __float2bfloat16(vv[j]);
        h[base + j] = hb;
        l[base + j] = __float2bfloat16(vv[j] - __bfloat162float(hb));
    }
}

// ---------------------------------------------------------------------------
// Flash-style fp32 attention (unchanged from round 1)
// ---------------------------------------------------------------------------
#define SMEM_ATTN (4 * 64 * 68 * 4)

__global__ __launch_bounds__(256) void attn_kernel(const float* __restrict__ prev,
                                                   const unsigned char* __restrict__ attn_mask,
                                                   const unsigned char* __restrict__ kpm,
                                                   float* __restrict__ out_logits)
{
    extern __shared__ float smattn[];
    float (*Qs)[68] = (float(*)[68])smattn;
    float (*Ks)[68] = (float(*)[68])(smattn + 64 * 68);
    float (*Vs)[68] = (float(*)[68])(smattn + 2 * 64 * 68);
    float (*Ps)[68] = (float(*)[68])(smattn + 3 * 64 * 68);

    const int tid = threadIdx.x;
    const int ty = tid >> 4;
    const int tx = tid & 15;
    const int bh = blockIdx.y;
    const int n = bh >> 4;
    const int r0 = blockIdx.x * 64;

    const int li = tid >> 4;
    const int dc = (tid & 15) * 4;

#pragma unroll
    for (int p = 0; p < 4; p++) {
        int i = li + p * 16;
        float4 v = *(const float4*)&g_q[((size_t)(bh * LL + r0 + i)) * DD + dc];
        Qs[dc + 0][i] = v.x;
        Qs[dc + 1][i] = v.y;
        Qs[dc + 2][i] = v.z;
        Qs[dc + 3][i] = v.w;
    }

    float o[4][4];
    float mrow[4], lrow[4];
#pragma unroll
    for (int i = 0; i < 4; i++) {
        mrow[i] = -INFINITY;
        lrow[i] = 0.f;
#pragma unroll
        for (int j = 0; j < 4; j++) o[i][j] = 0.f;
    }

    for (int s0 = 0; s0 < SS; s0 += 64) {
        __syncthreads();
#pragma unroll
        for (int p = 0; p < 4; p++) {
            int j = li + p * 16;
            float4 kv = *(const float4*)&g_k[((size_t)(bh * SS + s0 + j)) * DD + dc];
            Ks[dc + 0][j] = kv.x;
            Ks[dc + 1][j] = kv.y;
            Ks[dc + 2][j] = kv.z;
            Ks[dc + 3][j] = kv.w;
            float4 vv = *(const float4*)&g_v[((size_t)(bh * SS + s0 + j)) * DD + dc];
            *(float4*)&Vs[j][dc] = vv;
        }
        __syncthreads();

        float acc[4][4];
#pragma unroll
        for (int i = 0; i < 4; i++)
#pragma unroll
            for (int j = 0; j < 4; j++) acc[i][j] = 0.f;
#pragma unroll
        for (int d = 0; d < 64; d++) {
            float4 a = *(const float4*)&Qs[d][ty * 4];
            float4 b = *(const float4*)&Ks[d][tx * 4];
            float av[4] = {a.x, a.y, a.z, a.w};
            float bv[4] = {b.x, b.y, b.z, b.w};
#pragma unroll
            for (int i = 0; i < 4; i++)
#pragma unroll
                for (int j = 0; j < 4; j++)
                    acc[i][j] = fmaf(av[i], bv[j], acc[i][j]);
        }

        float sc[4];
#pragma unroll
        for (int ii = 0; ii < 4; ii++) {
            int row = r0 + ty * 4 + ii;
            size_t base = ((size_t)bh * LL + row) * SS + s0 + tx * 4;
            float4 pv = *(const float4*)&prev[base];
            const unsigned char* amp = &attn_mask[(size_t)row * SS + s0 + tx * 4];
            const unsigned char* kmp = &kpm[(size_t)n * SS + s0 + tx * 4];
            float lg[4];
            float pvv[4] = {pv.x, pv.y, pv.z, pv.w};
#pragma unroll
            for (int jj = 0; jj < 4; jj++) {
                bool msk = (amp[jj] != 0) || (kmp[jj] != 0);
                lg[jj] = msk ? -INFINITY : fmaf(acc[ii][jj], 0.125f, pvv[jj]);
            }
            *(float4*)&out_logits[base] = make_float4(lg[0], lg[1], lg[2], lg[3]);

            float tmax = fmaxf(fmaxf(lg[0], lg[1]), fmaxf(lg[2], lg[3]));
#pragma unroll
            for (int off = 8; off > 0; off >>= 1)
                tmax = fmaxf(tmax, __shfl_xor_sync(0xffffffffu, tmax, off));
            float mnew = fmaxf(mrow[ii], tmax);
            float scl = (mnew == -INFINITY) ? 1.f : expf(mrow[ii] - mnew);
            float psum = 0.f;
            float pj[4];
#pragma unroll
            for (int jj = 0; jj < 4; jj++) {
                float p = (mnew == -INFINITY) ? 0.f : expf(lg[jj] - mnew);
                pj[jj] = p;
                psum += p;
            }
#pragma unroll
            for (int off = 8; off > 0; off >>= 1)
                psum += __shfl_xor_sync(0xffffffffu, psum, off);
            lrow[ii] = lrow[ii] * scl + psum;
            mrow[ii] = mnew;
            sc[ii] = scl;
#pragma unroll
            for (int jj = 0; jj < 4; jj++)
                Ps[tx * 4 + jj][ty * 4 + ii] = pj[jj];
        }
        __syncthreads();

#pragma unroll
        for (int ii = 0; ii < 4; ii++)
#pragma unroll
            for (int dd = 0; dd < 4; dd++) o[ii][dd] *= sc[ii];
#pragma unroll
        for (int j = 0; j < 64; j++) {
            float4 a = *(const float4*)&Ps[j][ty * 4];
            float4 b = *(const float4*)&Vs[j][tx * 4];
            float av[4] = {a.x, a.y, a.z, a.w};
            float bv[4] = {b.x, b.y, b.z, b.w};
#pragma unroll
            for (int ii = 0; ii < 4; ii++)
#pragma unroll
                for (int dd = 0; dd < 4; dd++)
                    o[ii][dd] = fmaf(av[ii], bv[dd], o[ii][dd]);
        }
    }

#pragma unroll
    for (int ii = 0; ii < 4; ii++) {
        float inv = 1.f / lrow[ii];
        int row = r0 + ty * 4 + ii;
        float4 v = make_float4(o[ii][0] * inv, o[ii][1] * inv,
                               o[ii][2] * inv, o[ii][3] * inv);
        *(float4*)&g_o[((size_t)(bh * LL + row)) * DD + tx * 4] = v;
    }
}

// ---------------------------------------------------------------------------
extern "C" void kernel_launch(void* const* d_in, const int* in_sizes, int n_in,
                              void* d_out, int out_size)
{
    const float* query = (const float*)d_in[0];
    const float* key   = (const float*)d_in[1];
    const float* value = (const float*)d_in[2];
    const float* prev  = (const float*)d_in[3];
    const unsigned char* kpm = (const unsigned char*)d_in[4];
    const unsigned char* am  = (const unsigned char*)d_in[5];
    const float* Wq = (const float*)d_in[6];
    const float* Wk = (const float*)d_in[7];
    const float* Wv = (const float*)d_in[8];
    const float* Wo = (const float*)d_in[9];

    float* out = (float*)d_out;
    float* out_logits = out + (size_t)LL * NB * EE;

    float *gq, *gk, *gv, *go;
    __nv_bfloat16 *ah, *al, *bh, *bl;
    cudaGetSymbolAddress((void**)&gq, g_q);
    cudaGetSymbolAddress((void**)&gk, g_k);
    cudaGetSymbolAddress((void**)&gv, g_v);
    cudaGetSymbolAddress((void**)&go, g_o);
    cudaGetSymbolAddress((void**)&ah, g_ah);
    cudaGetSymbolAddress((void**)&al, g_al);
    cudaGetSymbolAddress((void**)&bh, g_bh);
    cudaGetSymbolAddress((void**)&bl, g_bl);

    cudaFuncSetAttribute(attn_kernel,
                         cudaFuncAttributeMaxDynamicSharedMemorySize, SMEM_ATTN);
    cudaFuncSetAttribute(gemm_mma_bf16x3,
                         cudaFuncAttributeMaxDynamicSharedMemorySize, GSM_TOTAL);

    const int nsplit4 = MROWS * EE / 4;
    const dim3 ggemm(EE / 128, MROWS / 128);   // (8, 32)
    const dim3 gtr(EE / 32, EE / 32);          // (32, 32)

    // Q projection
    wtrans_split<<<gtr, 256>>>(Wq, bh, bl);
    split_kernel<<<(nsplit4 + 255) / 256, 256>>>(query, ah, al, nsplit4);
    gemm_mma_bf16x3<<<ggemm, 256, GSM_TOTAL>>>(ah, al, bh, bl, gq, 1);
    // K projection
    wtrans_split<<<gtr, 256>>>(Wk, bh, bl);
    split_kernel<<<(nsplit4 + 255) / 256, 256>>>(key, ah, al, nsplit4);
    gemm_mma_bf16x3<<<ggemm, 256, GSM_TOTAL>>>(ah, al, bh, bl, gk, 1);
    // V projection
    wtrans_split<<<gtr, 256>>>(Wv, bh, bl);
    split_kernel<<<(nsplit4 + 255) / 256, 256>>>(value, ah, al, nsplit4);
    gemm_mma_bf16x3<<<ggemm, 256, GSM_TOTAL>>>(ah, al, bh, bl, gv, 1);

    // Attention (fp32 SIMT, writes logits + g_o)
    attn_kernel<<<dim3(LL / 64, BH), 256, SMEM_ATTN>>>(prev, am, kpm, out_logits);

    // Output projection
    wtrans_split<<<gtr, 256>>>(Wo, bh, bl);
    osplit_kernel<<<(nsplit4 + 255) / 256, 256>>>(go, ah, al);
    gemm_mma_bf16x3<<<ggemm, 256, GSM_TOTAL>>>(ah, al, bh, bl, out, 0);
}

// round 8
// speedup vs baseline: 2.7002x; 1.9883x over previous
#include <cuda_runtime.h>
#include <cuda_bf16.h>
#include <math.h>
#include <stdint.h>

// Problem constants
#define LL 2048
#define SS 2048
#define NB 2
#define HH 16
#define DD 64
#define EE 1024
#define BH 32          // NB*HH
#define MROWS 4096     // LL*NB

// ---------------------------------------------------------------------------
// Scratch (device globals; no allocation allowed)
// ---------------------------------------------------------------------------
__device__ __nv_bfloat16 g_qh[(size_t)BH * LL * DD];
__device__ __nv_bfloat16 g_ql[(size_t)BH * LL * DD];
__device__ __nv_bfloat16 g_kh[(size_t)BH * SS * DD];
__device__ __nv_bfloat16 g_kl[(size_t)BH * SS * DD];
__device__ __nv_bfloat16 g_vh[(size_t)BH * SS * DD];
__device__ __nv_bfloat16 g_vl[(size_t)BH * SS * DD];

__device__ __nv_bfloat16 g_ah[(size_t)MROWS * EE];
__device__ __nv_bfloat16 g_al[(size_t)MROWS * EE];
__device__ __nv_bfloat16 g_bh[(size_t)EE * EE];
__device__ __nv_bfloat16 g_bl[(size_t)EE * EE];

// ---------------------------------------------------------------------------
// Common PTX helpers
// ---------------------------------------------------------------------------
__device__ __forceinline__ uint32_t smem_u32(const void* p) {
    uint32_t a;
    asm("{ .reg .u64 t; cvta.to.shared.u64 t, %1; cvt.u32.u64 %0, t; }"
        : "=r"(a) : "l"(p));
    return a;
}

__device__ __forceinline__ void ldmatrix4(uint32_t* r, uint32_t addr) {
    asm volatile("ldmatrix.sync.aligned.m8n8.x4.shared.b16 {%0,%1,%2,%3}, [%4];"
                 : "=r"(r[0]), "=r"(r[1]), "=r"(r[2]), "=r"(r[3]) : "r"(addr));
}

__device__ __forceinline__ void ldmatrix4t(uint32_t* r, uint32_t addr) {
    asm volatile("ldmatrix.sync.aligned.m8n8.x4.trans.shared.b16 {%0,%1,%2,%3}, [%4];"
                 : "=r"(r[0]), "=r"(r[1]), "=r"(r[2]), "=r"(r[3]) : "r"(addr));
}

__device__ __forceinline__ void mma16816(float* c, const uint32_t* a,
                                         uint32_t b0, uint32_t b1) {
    asm volatile("mma.sync.aligned.m16n8k16.row.col.f32.bf16.bf16.f32 "
                 "{%0,%1,%2,%3}, {%4,%5,%6,%7}, {%8,%9}, {%0,%1,%2,%3};"
                 : "+f"(c[0]), "+f"(c[1]), "+f"(c[2]), "+f"(c[3])
                 : "r"(a[0]), "r"(a[1]), "r"(a[2]), "r"(a[3]), "r"(b0), "r"(b1));
}

#define CP_ASYNC16(dst, src) \
    asm volatile("cp.async.cg.shared.global [%0], [%1], 16;" :: "r"(dst), "l"(src))
#define CP_COMMIT() asm volatile("cp.async.commit_group;" ::: "memory")
#define CP_WAIT1()  asm volatile("cp.async.wait_group 1;" ::: "memory")

// ---------------------------------------------------------------------------
// mma.sync GEMM: C[4096x1024] = X*W via bf16x3 split (K' = 3*1024)
// CTA 128x128, 8 warps (2m x 4n), warp tile 64x32, 3-stage cp.async.
// mode 0: fp32 row-major; 1: bf16 hi/lo head-major.
// ---------------------------------------------------------------------------
#define NSTAGE 3
#define NIT 48
#define STAGE_BYTES 32768
#define AOFF 0
#define BOFF 16384
#define GSM_TOTAL (NSTAGE * STAGE_BYTES)

__device__ __forceinline__ void load_tile(int it, int buf, int tid, int m0, int n0,
                                          const __nv_bfloat16* __restrict__ Ah,
                                          const __nv_bfloat16* __restrict__ Al,
                                          const __nv_bfloat16* __restrict__ Bth,
                                          const __nv_bfloat16* __restrict__ Btl,
                                          uint32_t sb)
{
    const int term = it >> 4;
    const int kc = (it & 15) << 6;
    const __nv_bfloat16* As = (term == 1) ? Al : Ah;
    const __nv_bfloat16* Bs = (term == 2) ? Btl : Bth;
    const uint32_t abase = sb + buf * STAGE_BYTES + AOFF;
    const uint32_t bbase = sb + buf * STAGE_BYTES + BOFF;
#pragma unroll
    for (int i = 0; i < 8; i++) {
        int g = i * 256 + tid;
        int row = (g >> 3) & 127;
        int c = g & 7;
        const __nv_bfloat16* src;
        uint32_t dst;
        if (g < 1024) {
            src = As + (size_t)(m0 + row) * EE + kc + (c << 3);
            dst = abase + row * 128 + ((c ^ (row & 7)) << 4);
        } else {
            src = Bs + (size_t)(n0 + row) * EE + kc + (c << 3);
            dst = bbase + row * 128 + ((c ^ (row & 7)) << 4);
        }
        CP_ASYNC16(dst, src);
    }
}

__global__ void __launch_bounds__(256, 1) gemm_mma_bf16x3(
    const __nv_bfloat16* __restrict__ Ah, const __nv_bfloat16* __restrict__ Al,
    const __nv_bfloat16* __restrict__ Bth, const __nv_bfloat16* __restrict__ Btl,
    float* __restrict__ dstf, __nv_bfloat16* __restrict__ dsth,
    __nv_bfloat16* __restrict__ dstl, int mode)
{
    extern __shared__ __align__(1024) char sm[];
    const uint32_t sb = smem_u32(sm);
    const int tid = threadIdx.x;
    const int wid = tid >> 5, lane = tid & 31;
    const int wm = wid >> 2;
    const int wn = wid & 3;
    const int m0 = blockIdx.y * 128;
    const int n0 = blockIdx.x * 128;

    float acc[4][4][4];
#pragma unroll
    for (int i = 0; i < 4; i++)
#pragma unroll
        for (int j = 0; j < 4; j++)
#pragma unroll
            for (int k = 0; k < 4; k++) acc[i][j][k] = 0.f;

    load_tile(0, 0, tid, m0, n0, Ah, Al, Bth, Btl, sb);
    CP_COMMIT();
    load_tile(1, 1, tid, m0, n0, Ah, Al, Bth, Btl, sb);
    CP_COMMIT();

    const int a_r = (lane & 7) + ((lane >> 3) & 1) * 8;
    const int a_c8 = lane >> 4;
    const int b_r = (lane & 7) + (lane >> 4) * 8;
    const int b_c8 = (lane >> 3) & 1;

    for (int it = 0; it < NIT; ++it) {
        CP_WAIT1();
        __syncthreads();
        if (it + 2 < NIT)
            load_tile(it + 2, (it + 2) % NSTAGE, tid, m0, n0, Ah, Al, Bth, Btl, sb);
        CP_COMMIT();

        const int buf = it % NSTAGE;
        const uint32_t Ab = sb + buf * STAGE_BYTES + AOFF;
        const uint32_t Bb = sb + buf * STAGE_BYTES + BOFF;
#pragma unroll
        for (int ks = 0; ks < 4; ks++) {
            const int k0 = ks * 16;
            uint32_t a[4][4];
#pragma unroll
            for (int mt = 0; mt < 4; mt++) {
                int row = wm * 64 + mt * 16 + a_r;
                int col = k0 + 8 * a_c8;
                uint32_t addr = Ab + row * 128 + (((col >> 3) ^ (row & 7)) << 4);
                ldmatrix4(a[mt], addr);
            }
            uint32_t b[2][4];
#pragma unroll
            for (int bt = 0; bt < 2; bt++) {
                int row = wn * 32 + bt * 16 + b_r;
                int col = k0 + 8 * b_c8;
                uint32_t addr = Bb + row * 128 + (((col >> 3) ^ (row & 7)) << 4);
                ldmatrix4(b[bt], addr);
            }
#pragma unroll
            for (int mt = 0; mt < 4; mt++) {
#pragma unroll
                for (int nt = 0; nt < 4; nt++) {
                    uint32_t b0 = b[nt >> 1][(nt & 1) * 2];
                    uint32_t b1 = b[nt >> 1][(nt & 1) * 2 + 1];
                    mma16816(acc[mt][nt], a[mt], b0, b1);
                }
            }
        }
    }

    // Epilogue
#pragma unroll
    for (int mt = 0; mt < 4; mt++) {
#pragma unroll
        for (int nt = 0; nt < 4; nt++) {
            int m = m0 + wm * 64 + mt * 16 + (lane >> 2);
            int n = n0 + wn * 32 + nt * 8 + 2 * (lane & 3);
#pragma unroll
            for (int half = 0; half < 2; half++) {
                int mm = m + half * 8;
                float2 v = make_float2(acc[mt][nt][half * 2],
                                       acc[mt][nt][half * 2 + 1]);
                if (mode == 0) {
                    *(float2*)&dstf[(size_t)mm * EE + n] = v;
                } else {
                    int t = mm >> 1, nb = mm & 1;
                    int h = n >> 6, d = n & 63;
                    size_t idx = ((size_t)((nb * HH + h) * LL + t)) * DD + d;
                    __nv_bfloat162 hv;
                    hv.x = __float2bfloat16(v.x);
                    hv.y = __float2bfloat16(v.y);
                    *(__nv_bfloat162*)&dsth[idx] = hv;
                    __nv_bfloat162 lv;
                    lv.x = __float2bfloat16(v.x - __bfloat162float(hv.x));
                    lv.y = __float2bfloat16(v.y - __bfloat162float(hv.y));
                    *(__nv_bfloat162*)&dstl[idx] = lv;
                }
            }
        }
    }
}

// ---------------------------------------------------------------------------
// Conversion kernels
// ---------------------------------------------------------------------------
__global__ void __launch_bounds__(256) split_kernel(const float* __restrict__ x,
                                                    __nv_bfloat16* __restrict__ h,
                                                    __nv_bfloat16* __restrict__ l,
                                                    int n4)
{
    int i = blockIdx.x * 256 + threadIdx.x;
    if (i >= n4) return;
    float4 v = ((const float4*)x)[i];
    float vv[4] = {v.x, v.y, v.z, v.w};
    __nv_bfloat162 hh[2], ll[2];
#pragma unroll
    for (int j = 0; j < 2; j++) {
        __nv_bfloat16 h0 = __float2bfloat16(vv[2 * j]);
        __nv_bfloat16 h1 = __float2bfloat16(vv[2 * j + 1]);
        __nv_bfloat16 l0 = __float2bfloat16(vv[2 * j] - __bfloat162float(h0));
        __nv_bfloat16 l1 = __float2bfloat16(vv[2 * j + 1] - __bfloat162float(h1));
        hh[j] = __nv_bfloat162(h0, h1);
        ll[j] = __nv_bfloat162(l0, l1);
    }
    *(__nv_bfloat162*)(h + 4 * (size_t)i)     = hh[0];
    *(__nv_bfloat162*)(h + 4 * (size_t)i + 2) = hh[1];
    *(__nv_bfloat162*)(l + 4 * (size_t)i)     = ll[0];
    *(__nv_bfloat162*)(l + 4 * (size_t)i + 2) = ll[1];
}

// W[k][n] -> Wt[n][k] bf16 hi/lo
__global__ void __launch_bounds__(256) wtrans_split(const float* __restrict__ W,
                                                    __nv_bfloat16* __restrict__ th,
                                                    __nv_bfloat16* __restrict__ tl)
{
    __shared__ float t[32][33];
    const int n0 = blockIdx.x * 32, k0 = blockIdx.y * 32;
    const int tx = threadIdx.x & 31, ty = threadIdx.x >> 5;
#pragma unroll
    for (int j = 0; j < 32; j += 8)
        t[ty + j][tx] = W[(size_t)(k0 + ty + j) * EE + n0 + tx];
    __syncthreads();
#pragma unroll
    for (int j = 0; j < 32; j += 8) {
        float v = t[tx][ty + j];
        __nv_bfloat16 h = __float2bfloat16(v);
        __nv_bfloat16 l = __float2bfloat16(v - __bfloat162float(h));
        th[(size_t)(n0 + ty + j) * EE + k0 + tx] = h;
        tl[(size_t)(n0 + ty + j) * EE + k0 + tx] = l;
    }
}

// ---------------------------------------------------------------------------
// mma.sync flash attention.
// CTA: 128 q rows x full S sweep; 8 warps: wm=wid>>1 (32 rows), wn=wid&1 (64 s).
// QK: bf16x3 ([Qh|Ql|Qh] x [Kh|Kh|Kl]); PV: bf16x3 (Ph.Vh + Pl.Vh + Ph.Vl).
// Softmax without max-subtraction (logits are O(10), no overflow).
// smem: Qh 16K | Ql 16K | 2 stages x (Kh|Kl|Vh|Vl 64K) | lsum 1K
// ---------------------------------------------------------------------------
#define ASTG(b) (32768 + (b) * 65536)
#define ALS 163840
#define ASM_TOTAL (163840 + 1024)

__global__ void __launch_bounds__(256, 1) attn_mma(
    const __nv_bfloat16* __restrict__ Qh, const __nv_bfloat16* __restrict__ Ql,
    const __nv_bfloat16* __restrict__ Kh, const __nv_bfloat16* __restrict__ Kl,
    const __nv_bfloat16* __restrict__ Vh, const __nv_bfloat16* __restrict__ Vl,
    const float* __restrict__ prev,
    const unsigned char* __restrict__ am, const unsigned char* __restrict__ kpm,
    float* __restrict__ out_logits,
    __nv_bfloat16* __restrict__ oh, __nv_bfloat16* __restrict__ ol)
{
    extern __shared__ __align__(1024) char sm[];
    const uint32_t sb = smem_u32(sm);
    const int tid = threadIdx.x, wid = tid >> 5, lane = tid & 31;
    const int wm = wid >> 1, wn = wid & 1;
    const int bh = blockIdx.y, nb = bh >> 4, hh = bh & 15;
    const int q0 = blockIdx.x * 128;

    const int a_r = (lane & 7) + ((lane >> 3) & 1) * 8;
    const int a_c8 = lane >> 4;
    const int b_r = (lane & 7) + (lane >> 4) * 8;
    const int b_c8 = (lane >> 3) & 1;

    // Load Q (Qh then Ql): 2048 16B chunks
#pragma unroll
    for (int i = 0; i < 8; i++) {
        int g = i * 256 + tid;
        int row = (g >> 3) & 127, c = g & 7;
        const __nv_bfloat16* src = ((i >> 2) ? Ql : Qh) +
            ((size_t)bh * SS + q0 + row) * DD + (c << 3);
        uint32_t dst = sb + (i >> 2) * 16384 + row * 128 + ((c ^ (row & 7)) << 4);
        CP_ASYNC16(dst, src);
    }
    // Stage 0 (Kh, Kl, Vh, Vl): 4096 chunks
#pragma unroll
    for (int i = 0; i < 16; i++) {
        int g = i * 256 + tid;
        int which = g >> 10, local = g & 1023;
        int row = local >> 3, c = local & 7;
        const __nv_bfloat16* base =
            (which == 0) ? Kh : (which == 1) ? Kl : (which == 2) ? Vh : Vl;
        const __nv_bfloat16* src = base + ((size_t)bh * SS + row) * DD + (c << 3);
        uint32_t dst = sb + ASTG(0) + which * 16384 + row * 128 + ((c ^ (row & 7)) << 4);
        CP_ASYNC16(dst, src);
    }
    CP_COMMIT();

    float accO[2][8][4];
#pragma unroll
    for (int i = 0; i < 2; i++)
#pragma unroll
        for (int j = 0; j < 8; j++)
#pragma unroll
            for (int k = 0; k < 4; k++) accO[i][j][k] = 0.f;
    float psum[4] = {0.f, 0.f, 0.f, 0.f};

    for (int it = 0; it < 16; ++it) {
        const int s0 = it * 128, buf = it & 1;
        if (it + 1 < 16) {
            const int nbuf = (it + 1) & 1, ns0 = (it + 1) * 128;
#pragma unroll
            for (int i = 0; i < 16; i++) {
                int g = i * 256 + tid;
                int which = g >> 10, local = g & 1023;
                int row = local >> 3, c = local & 7;
                const __nv_bfloat16* base =
                    (which == 0) ? Kh : (which == 1) ? Kl : (which == 2) ? Vh : Vl;
                const __nv_bfloat16* src = base +
                    ((size_t)bh * SS + ns0 + row) * DD + (c << 3);
                uint32_t dst = sb + ASTG(nbuf) + which * 16384 + row * 128 +
                               ((c ^ (row & 7)) << 4);
                CP_ASYNC16(dst, src);
            }
        }
        CP_COMMIT();
        CP_WAIT1();
        __syncthreads();

        // ---- S = Q K^T (3-term split) ----
        float accS[2][8][4];
#pragma unroll
        for (int i = 0; i < 2; i++)
#pragma unroll
            for (int j = 0; j < 8; j++)
#pragma unroll
                for (int k = 0; k < 4; k++) accS[i][j][k] = 0.f;

        const uint32_t KB = sb + ASTG(buf);
#pragma unroll
        for (int kk = 0; kk < 12; kk++) {
            const int term = kk >> 2, kc = (kk & 3) * 16;
            const uint32_t Ab = sb + (term == 1 ? 16384 : 0);
            const uint32_t Bb = KB + (term == 2 ? 16384 : 0);
            uint32_t a[2][4];
#pragma unroll
            for (int mt = 0; mt < 2; mt++) {
                int row = wm * 32 + mt * 16 + a_r;
                int col = kc + 8 * a_c8;
                ldmatrix4(a[mt], Ab + row * 128 + (((col >> 3) ^ (row & 7)) << 4));
            }
            uint32_t b[4][4];
#pragma unroll
            for (int g = 0; g < 4; g++) {
                int row = wn * 64 + g * 16 + b_r;
                int col = kc + 8 * b_c8;
                ldmatrix4(b[g], Bb + row * 128 + (((col >> 3) ^ (row & 7)) << 4));
            }
#pragma unroll
            for (int mt = 0; mt < 2; mt++)
#pragma unroll
                for (int nt = 0; nt < 8; nt++)
                    mma16816(accS[mt][nt], a[mt],
                             b[nt >> 1][(nt & 1) * 2], b[nt >> 1][(nt & 1) * 2 + 1]);
        }

        // ---- logits + exp + PV (3-term) per 16-wide k-slice ----
        const uint32_t VB  = KB + 32768;
        const uint32_t VLB = KB + 49152;
#pragma unroll
        for (int ks = 0; ks < 4; ks++) {
            uint32_t pA[2][4], pAl[2][4];
#pragma unroll
            for (int mt = 0; mt < 2; mt++) {
#pragma unroll
                for (int sub = 0; sub < 2; sub++) {
                    const int nt = 2 * ks + sub;
                    const int row0 = q0 + wm * 32 + mt * 16 + (lane >> 2);
                    const int col = s0 + wn * 64 + nt * 8 + 2 * (lane & 3);
                    uchar2 kv2 = *(const uchar2*)&kpm[(size_t)nb * SS + col];
#pragma unroll
                    for (int half = 0; half < 2; half++) {
                        const int row = row0 + half * 8;
                        size_t base = ((size_t)bh * LL + row) * SS + col;
                        float2 pv = *(const float2*)&prev[base];
                        uchar2 av2 = *(const uchar2*)&am[(size_t)row * SS + col];
                        float c0 = accS[mt][nt][half * 2];
                        float c1 = accS[mt][nt][half * 2 + 1];
                        float lg0 = (av2.x | kv2.x) ? -INFINITY : fmaf(c0, 0.125f, pv.x);
                        float lg1 = (av2.y | kv2.y) ? -INFINITY : fmaf(c1, 0.125f, pv.y);
                        *(float2*)&out_logits[base] = make_float2(lg0, lg1);
                        float p0 = __expf(lg0), p1 = __expf(lg1);
                        psum[mt * 2 + half] += p0 + p1;
                        __nv_bfloat162 pb, plb;
                        pb.x = __float2bfloat16(p0);
                        pb.y = __float2bfloat16(p1);
                        plb.x = __float2bfloat16(p0 - __bfloat162float(pb.x));
                        plb.y = __float2bfloat16(p1 - __bfloat162float(pb.y));
                        pA[mt][sub * 2 + half]  = *(uint32_t*)&pb;
                        pAl[mt][sub * 2 + half] = *(uint32_t*)&plb;
                    }
                }
            }
            uint32_t vb[4][4], vbl[4][4];
#pragma unroll
            for (int dg = 0; dg < 4; dg++) {
                int row = wn * 64 + ks * 16 + a_r;
                int chunk = dg * 2 + (lane >> 4);
                ldmatrix4t(vb[dg],  VB  + row * 128 + ((chunk ^ (row & 7)) << 4));
                ldmatrix4t(vbl[dg], VLB + row * 128 + ((chunk ^ (row & 7)) << 4));
            }
#pragma unroll
            for (int mt = 0; mt < 2; mt++)
#pragma unroll
                for (int dn = 0; dn < 8; dn++) {
                    uint32_t bh0 = vb[dn >> 1][(dn & 1) * 2];
                    uint32_t bh1 = vb[dn >> 1][(dn & 1) * 2 + 1];
                    mma16816(accO[mt][dn], pA[mt], bh0, bh1);
                    mma16816(accO[mt][dn], pAl[mt], bh0, bh1);
                    mma16816(accO[mt][dn], pA[mt],
                             vbl[dn >> 1][(dn & 1) * 2], vbl[dn >> 1][(dn & 1) * 2 + 1]);
                }
        }
        __syncthreads();
    }

    // ---- epilogue: row-sum reduce, cross-warp O sum, normalize, split-write ----
    float* ls = (float*)(sm + ALS);
#pragma unroll
    for (int idx = 0; idx < 4; idx++) {
        float v = psum[idx];
        v += __shfl_xor_sync(0xffffffffu, v, 1);
        v += __shfl_xor_sync(0xffffffffu, v, 2);
        int row = wm * 32 + (idx >> 1) * 16 + (idx & 1) * 8 + (lane >> 2);
        if ((lane & 3) == 0) ls[wn * 128 + row] = v;
    }
    __syncthreads();
    float* ob = (float*)(sm + 32768);      // reuse stage0 (32KB)
    if (wn == 1) {
#pragma unroll
        for (int mt = 0; mt < 2; mt++)
#pragma unroll
            for (int dn = 0; dn < 8; dn++) {
                int rl = wm * 32 + mt * 16 + (lane >> 2);
                int col = dn * 8 + 2 * (lane & 3);
                *(float2*)&ob[rl * 64 + col] =
                    make_float2(accO[mt][dn][0], accO[mt][dn][1]);
                *(float2*)&ob[(rl + 8) * 64 + col] =
                    make_float2(accO[mt][dn][2], accO[mt][dn][3]);
            }
    }
    __syncthreads();
    if (wn == 0) {
#pragma unroll
        for (int mt = 0; mt < 2; mt++)
#pragma unroll
            for (int dn = 0; dn < 8; dn++)
#pragma unroll
                for (int half = 0; half < 2; half++) {
                    int rl = wm * 32 + mt * 16 + (lane >> 2) + half * 8;
                    int col = dn * 8 + 2 * (lane & 3);
                    float2 o2 = *(float2*)&ob[rl * 64 + col];
                    float inv = 1.f / (ls[rl] + ls[128 + rl]);
                    float o0 = (accO[mt][dn][half * 2] + o2.x) * inv;
                    float o1 = (accO[mt][dn][half * 2 + 1] + o2.y) * inv;
                    size_t r = (size_t)(q0 + rl) * NB + nb;
                    size_t cg = hh * 64 + col;
                    __nv_bfloat162 hv, lv;
                    hv.x = __float2bfloat16(o0);
                    hv.y = __float2bfloat16(o1);
                    lv.x = __float2bfloat16(o0 - __bfloat162float(hv.x));
                    lv.y = __float2bfloat16(o1 - __bfloat162float(hv.y));
                    *(__nv_bfloat162*)&oh[r * EE + cg] = hv;
                    *(__nv_bfloat162*)&ol[r * EE + cg] = lv;
                }
    }
}

// ---------------------------------------------------------------------------
extern "C" void kernel_launch(void* const* d_in, const int* in_sizes, int n_in,
                              void* d_out, int out_size)
{
    const float* query = (const float*)d_in[0];
    const float* key   = (const float*)d_in[1];
    const float* value = (const float*)d_in[2];
    const float* prev  = (const float*)d_in[3];
    const unsigned char* kpm = (const unsigned char*)d_in[4];
    const unsigned char* am  = (const unsigned char*)d_in[5];
    const float* Wq = (const float*)d_in[6];
    const float* Wk = (const float*)d_in[7];
    const float* Wv = (const float*)d_in[8];
    const float* Wo = (const float*)d_in[9];

    float* out = (float*)d_out;
    float* out_logits = out + (size_t)LL * NB * EE;

    __nv_bfloat16 *qh, *ql, *kh, *kl, *vh, *vl, *ah, *al, *bh, *bl;
    cudaGetSymbolAddress((void**)&qh, g_qh);
    cudaGetSymbolAddress((void**)&ql, g_ql);
    cudaGetSymbolAddress((void**)&kh, g_kh);
    cudaGetSymbolAddress((void**)&kl, g_kl);
    cudaGetSymbolAddress((void**)&vh, g_vh);
    cudaGetSymbolAddress((void**)&vl, g_vl);
    cudaGetSymbolAddress((void**)&ah, g_ah);
    cudaGetSymbolAddress((void**)&al, g_al);
    cudaGetSymbolAddress((void**)&bh, g_bh);
    cudaGetSymbolAddress((void**)&bl, g_bl);

    cudaFuncSetAttribute(gemm_mma_bf16x3,
                         cudaFuncAttributeMaxDynamicSharedMemorySize, GSM_TOTAL);
    cudaFuncSetAttribute(attn_mma,
                         cudaFuncAttributeMaxDynamicSharedMemorySize, ASM_TOTAL);

    const int nsplit4 = MROWS * EE / 4;
    const dim3 ggemm(EE / 128, MROWS / 128);   // (8, 32)
    const dim3 gtr(EE / 32, EE / 32);          // (32, 32)

    // Q projection -> bf16 hi/lo head-major
    wtrans_split<<<gtr, 256>>>(Wq, bh, bl);
    split_kernel<<<(nsplit4 + 255) / 256, 256>>>(query, ah, al, nsplit4);
    gemm_mma_bf16x3<<<ggemm, 256, GSM_TOTAL>>>(ah, al, bh, bl, nullptr, qh, ql, 1);
    // K projection
    wtrans_split<<<gtr, 256>>>(Wk, bh, bl);
    split_kernel<<<(nsplit4 + 255) / 256, 256>>>(key, ah, al, nsplit4);
    gemm_mma_bf16x3<<<ggemm, 256, GSM_TOTAL>>>(ah, al, bh, bl, nullptr, kh, kl, 1);
    // V projection -> bf16 hi/lo head-major
    wtrans_split<<<gtr, 256>>>(Wv, bh, bl);
    split_kernel<<<(nsplit4 + 255) / 256, 256>>>(value, ah, al, nsplit4);
    gemm_mma_bf16x3<<<ggemm, 256, GSM_TOTAL>>>(ah, al, bh, bl, nullptr, vh, vl, 1);

    // Attention (writes logits + attn-out split into ah/al)
    attn_mma<<<dim3(LL / 128, BH), 256, ASM_TOTAL>>>(qh, ql, kh, kl, vh, vl,
                                                     prev, am, kpm,
                                                     out_logits, ah, al);

    // Output projection (fp32 row-major)
    wtrans_split<<<gtr, 256>>>(Wo, bh, bl);
    gemm_mma_bf16x3<<<ggemm, 256, GSM_TOTAL>>>(ah, al, bh, bl, out, nullptr, nullptr, 0);
}

// round 9
// speedup vs baseline: 2.8288x; 1.0476x over previous
#include <cuda_runtime.h>
#include <cuda_bf16.h>
#include <math.h>
#include <stdint.h>

// Problem constants
#define LL 2048
#define SS 2048
#define NB 2
#define HH 16
#define DD 64
#define EE 1024
#define BH 32          // NB*HH
#define MROWS 4096     // LL*NB

// ---------------------------------------------------------------------------
// Scratch (device globals; no allocation allowed)
// ---------------------------------------------------------------------------
__device__ __nv_bfloat16 g_qh[(size_t)BH * LL * DD];
__device__ __nv_bfloat16 g_ql[(size_t)BH * LL * DD];
__device__ __nv_bfloat16 g_kh[(size_t)BH * SS * DD];
__device__ __nv_bfloat16 g_kl[(size_t)BH * SS * DD];
__device__ __nv_bfloat16 g_vh[(size_t)BH * SS * DD];
__device__ __nv_bfloat16 g_vl[(size_t)BH * SS * DD];

__device__ __nv_bfloat16 g_a3h[3][(size_t)MROWS * EE];   // q/k/v input splits; [0] reused for attn out
__device__ __nv_bfloat16 g_a3l[3][(size_t)MROWS * EE];
__device__ __nv_bfloat16 g_w3h[4][(size_t)EE * EE];      // Wq, Wk, Wv, Wo transposed splits
__device__ __nv_bfloat16 g_w3l[4][(size_t)EE * EE];

// ---------------------------------------------------------------------------
// Common PTX helpers
// ---------------------------------------------------------------------------
__device__ __forceinline__ uint32_t smem_u32(const void* p) {
    uint32_t a;
    asm("{ .reg .u64 t; cvta.to.shared.u64 t, %1; cvt.u32.u64 %0, t; }"
        : "=r"(a) : "l"(p));
    return a;
}

__device__ __forceinline__ void ldmatrix4(uint32_t* r, uint32_t addr) {
    asm volatile("ldmatrix.sync.aligned.m8n8.x4.shared.b16 {%0,%1,%2,%3}, [%4];"
                 : "=r"(r[0]), "=r"(r[1]), "=r"(r[2]), "=r"(r[3]) : "r"(addr));
}

__device__ __forceinline__ void ldmatrix4t(uint32_t* r, uint32_t addr) {
    asm volatile("ldmatrix.sync.aligned.m8n8.x4.trans.shared.b16 {%0,%1,%2,%3}, [%4];"
                 : "=r"(r[0]), "=r"(r[1]), "=r"(r[2]), "=r"(r[3]) : "r"(addr));
}

__device__ __forceinline__ void mma16816(float* c, const uint32_t* a,
                                         uint32_t b0, uint32_t b1) {
    asm volatile("mma.sync.aligned.m16n8k16.row.col.f32.bf16.bf16.f32 "
                 "{%0,%1,%2,%3}, {%4,%5,%6,%7}, {%8,%9}, {%0,%1,%2,%3};"
                 : "+f"(c[0]), "+f"(c[1]), "+f"(c[2]), "+f"(c[3])
                 : "r"(a[0]), "r"(a[1]), "r"(a[2]), "r"(a[3]), "r"(b0), "r"(b1));
}

// pack two f32 -> bf16x2 (f0 in low half, f1 in high half), RN
__device__ __forceinline__ uint32_t pk_bf16x2(float f0, float f1) {
    uint32_t r;
    asm("cvt.rn.bf16x2.f32 %0, %2, %1;" : "=r"(r) : "f"(f0), "f"(f1));
    return r;
}

#define CP_ASYNC16(dst, src) \
    asm volatile("cp.async.cg.shared.global [%0], [%1], 16;" :: "r"(dst), "l"(src))
#define CP_COMMIT() asm volatile("cp.async.commit_group;" ::: "memory")
#define CP_WAIT1()  asm volatile("cp.async.wait_group 1;" ::: "memory")

// ---------------------------------------------------------------------------
// mma.sync GEMM: C[4096x1024] = X*W via bf16x3 split (K' = 3*1024)
// CTA 128x128, 8 warps (2m x 4n), warp tile 64x32, 3-stage cp.async, 2 CTA/SM.
// blockIdx.z selects the problem instance (merged Q/K/V launch).
// mode 0: fp32 row-major; 1: bf16 hi/lo head-major.
// ---------------------------------------------------------------------------
#define NSTAGE 3
#define NIT 48
#define STAGE_BYTES 32768
#define BOFF 16384
#define GSM_TOTAL (NSTAGE * STAGE_BYTES)

struct GemmArgs {
    const __nv_bfloat16 *ah, *al, *bth, *btl;
    __nv_bfloat16 *dsth, *dstl;
};
struct GemmArgs3 { GemmArgs g[3]; };

__device__ __forceinline__ void load_tile(int it, int buf, int tid, int m0, int n0,
                                          const __nv_bfloat16* __restrict__ Ah,
                                          const __nv_bfloat16* __restrict__ Al,
                                          const __nv_bfloat16* __restrict__ Bth,
                                          const __nv_bfloat16* __restrict__ Btl,
                                          uint32_t sb)
{
    const int term = it >> 4;
    const int kc = (it & 15) << 6;
    const __nv_bfloat16* As = (term == 1) ? Al : Ah;
    const __nv_bfloat16* Bs = (term == 2) ? Btl : Bth;
    const uint32_t abase = sb + buf * STAGE_BYTES;
    const uint32_t bbase = abase + BOFF;
#pragma unroll
    for (int i = 0; i < 8; i++) {
        int g = i * 256 + tid;
        int row = (g >> 3) & 127;
        int c = g & 7;
        const __nv_bfloat16* src;
        uint32_t dst;
        if (g < 1024) {
            src = As + (size_t)(m0 + row) * EE + kc + (c << 3);
            dst = abase + row * 128 + ((c ^ (row & 7)) << 4);
        } else {
            src = Bs + (size_t)(n0 + row) * EE + kc + (c << 3);
            dst = bbase + row * 128 + ((c ^ (row & 7)) << 4);
        }
        CP_ASYNC16(dst, src);
    }
}

__global__ void __launch_bounds__(256, 2) gemm_mma_bf16x3(
    GemmArgs3 A, float* __restrict__ dstf, int mode)
{
    extern __shared__ __align__(1024) char sm[];
    const uint32_t sb = smem_u32(sm);
    const GemmArgs ga = A.g[blockIdx.z];
    const __nv_bfloat16* __restrict__ Ah  = ga.ah;
    const __nv_bfloat16* __restrict__ Al  = ga.al;
    const __nv_bfloat16* __restrict__ Bth = ga.bth;
    const __nv_bfloat16* __restrict__ Btl = ga.btl;
    const int tid = threadIdx.x;
    const int wid = tid >> 5, lane = tid & 31;
    const int wm = wid >> 2;
    const int wn = wid & 3;
    const int m0 = blockIdx.y * 128;
    const int n0 = blockIdx.x * 128;

    float acc[4][4][4];
#pragma unroll
    for (int i = 0; i < 4; i++)
#pragma unroll
        for (int j = 0; j < 4; j++)
#pragma unroll
            for (int k = 0; k < 4; k++) acc[i][j][k] = 0.f;

    load_tile(0, 0, tid, m0, n0, Ah, Al, Bth, Btl, sb);
    CP_COMMIT();
    load_tile(1, 1, tid, m0, n0, Ah, Al, Bth, Btl, sb);
    CP_COMMIT();

    const int a_r = (lane & 7) + ((lane >> 3) & 1) * 8;
    const int a_c8 = lane >> 4;
    const int b_r = (lane & 7) + (lane >> 4) * 8;
    const int b_c8 = (lane >> 3) & 1;

    for (int it = 0; it < NIT; ++it) {
        CP_WAIT1();
        __syncthreads();
        if (it + 2 < NIT)
            load_tile(it + 2, (it + 2) % NSTAGE, tid, m0, n0, Ah, Al, Bth, Btl, sb);
        CP_COMMIT();

        const int buf = it % NSTAGE;
        const uint32_t Ab = sb + buf * STAGE_BYTES;
        const uint32_t Bb = Ab + BOFF;
#pragma unroll
        for (int ks = 0; ks < 4; ks++) {
            const int k0 = ks * 16;
            uint32_t a[4][4];
#pragma unroll
            for (int mt = 0; mt < 4; mt++) {
                int row = wm * 64 + mt * 16 + a_r;
                int col = k0 + 8 * a_c8;
                uint32_t addr = Ab + row * 128 + (((col >> 3) ^ (row & 7)) << 4);
                ldmatrix4(a[mt], addr);
            }
            uint32_t b[2][4];
#pragma unroll
            for (int bt = 0; bt < 2; bt++) {
                int row = wn * 32 + bt * 16 + b_r;
                int col = k0 + 8 * b_c8;
                uint32_t addr = Bb + row * 128 + (((col >> 3) ^ (row & 7)) << 4);
                ldmatrix4(b[bt], addr);
            }
#pragma unroll
            for (int mt = 0; mt < 4; mt++) {
#pragma unroll
                for (int nt = 0; nt < 4; nt++) {
                    uint32_t b0 = b[nt >> 1][(nt & 1) * 2];
                    uint32_t b1 = b[nt >> 1][(nt & 1) * 2 + 1];
                    mma16816(acc[mt][nt], a[mt], b0, b1);
                }
            }
        }
    }

    // Epilogue
#pragma unroll
    for (int mt = 0; mt < 4; mt++) {
#pragma unroll
        for (int nt = 0; nt < 4; nt++) {
            int m = m0 + wm * 64 + mt * 16 + (lane >> 2);
            int n = n0 + wn * 32 + nt * 8 + 2 * (lane & 3);
#pragma unroll
            for (int half = 0; half < 2; half++) {
                int mm = m + half * 8;
                float v0 = acc[mt][nt][half * 2];
                float v1 = acc[mt][nt][half * 2 + 1];
                if (mode == 0) {
                    *(float2*)&dstf[(size_t)mm * EE + n] = make_float2(v0, v1);
                } else {
                    int t = mm >> 1, nb = mm & 1;
                    int h = n >> 6, d = n & 63;
                    size_t idx = ((size_t)((nb * HH + h) * LL + t)) * DD + d;
                    uint32_t hv = pk_bf16x2(v0, v1);
                    float r0 = v0 - __uint_as_float(hv << 16);
                    float r1 = v1 - __uint_as_float(hv & 0xffff0000u);
                    uint32_t lv = pk_bf16x2(r0, r1);
                    *(uint32_t*)&ga.dsth[idx] = hv;
                    *(uint32_t*)&ga.dstl[idx] = lv;
                }
            }
        }
    }
}

// ---------------------------------------------------------------------------
// Conversion kernels (merged over blockIdx.z)
// ---------------------------------------------------------------------------
struct SplitArgs {
    const float* x[3];
    __nv_bfloat16 *h[3], *l[3];
};

__global__ void __launch_bounds__(256) split_kernel(SplitArgs S, int n4)
{
    int i = blockIdx.x * 256 + threadIdx.x;
    if (i >= n4) return;
    const int z = blockIdx.z;
    float4 v = ((const float4*)S.x[z])[i];
    uint32_t h0 = pk_bf16x2(v.x, v.y);
    uint32_t h1 = pk_bf16x2(v.z, v.w);
    float r0 = v.x - __uint_as_float(h0 << 16);
    float r1 = v.y - __uint_as_float(h0 & 0xffff0000u);
    float r2 = v.z - __uint_as_float(h1 << 16);
    float r3 = v.w - __uint_as_float(h1 & 0xffff0000u);
    uint32_t l0 = pk_bf16x2(r0, r1);
    uint32_t l1 = pk_bf16x2(r2, r3);
    *(uint2*)(S.h[z] + 4 * (size_t)i) = make_uint2(h0, h1);
    *(uint2*)(S.l[z] + 4 * (size_t)i) = make_uint2(l0, l1);
}

struct WArgs {
    const float* W[4];
    __nv_bfloat16 *th[4], *tl[4];
};

// W[k][n] -> Wt[n][k] bf16 hi/lo
__global__ void __launch_bounds__(256) wtrans_split(WArgs WA)
{
    __shared__ float t[32][33];
    const int z = blockIdx.z;
    const float* __restrict__ W = WA.W[z];
    const int n0 = blockIdx.x * 32, k0 = blockIdx.y * 32;
    const int tx = threadIdx.x & 31, ty = threadIdx.x >> 5;
#pragma unroll
    for (int j = 0; j < 32; j += 8)
        t[ty + j][tx] = W[(size_t)(k0 + ty + j) * EE + n0 + tx];
    __syncthreads();
#pragma unroll
    for (int j = 0; j < 32; j += 8) {
        float v = t[tx][ty + j];
        __nv_bfloat16 h = __float2bfloat16(v);
        __nv_bfloat16 l = __float2bfloat16(v - __bfloat162float(h));
        WA.th[z][(size_t)(n0 + ty + j) * EE + k0 + tx] = h;
        WA.tl[z][(size_t)(n0 + ty + j) * EE + k0 + tx] = l;
    }
}

// ---------------------------------------------------------------------------
// mma.sync flash attention.
// CTA: 128 q rows x full S sweep; 8 warps: wm=wid>>1 (32 rows), wn=wid&1 (64 s).
// QK: bf16x3 ([Qh|Ql|Qh] x [Kh|Kh|Kl]); PV: bf16x3 (Ph.Vh + Pl.Vh + Ph.Vl).
// Softmax without max-subtraction (logits are O(10), no overflow).
// smem: Qh 16K | Ql 16K | 2 stages x (Kh|Kl|Vh|Vl 64K) | lsum 1K
// ---------------------------------------------------------------------------
#define ASTG(b) (32768 + (b) * 65536)
#define ALS 163840
#define ASM_TOTAL (163840 + 1024)

__global__ void __launch_bounds__(256, 1) attn_mma(
    const __nv_bfloat16* __restrict__ Qh, const __nv_bfloat16* __restrict__ Ql,
    const __nv_bfloat16* __restrict__ Kh, const __nv_bfloat16* __restrict__ Kl,
    const __nv_bfloat16* __restrict__ Vh, const __nv_bfloat16* __restrict__ Vl,
    const float* __restrict__ prev,
    const unsigned char* __restrict__ am, const unsigned char* __restrict__ kpm,
    float* __restrict__ out_logits,
    __nv_bfloat16* __restrict__ oh, __nv_bfloat16* __restrict__ ol)
{
    extern __shared__ __align__(1024) char sm[];
    const uint32_t sb = smem_u32(sm);
    const int tid = threadIdx.x, wid = tid >> 5, lane = tid & 31;
    const int wm = wid >> 1, wn = wid & 1;
    const int bh = blockIdx.y, nb = bh >> 4, hh = bh & 15;
    const int q0 = blockIdx.x * 128;

    const int a_r = (lane & 7) + ((lane >> 3) & 1) * 8;
    const int a_c8 = lane >> 4;
    const int b_r = (lane & 7) + (lane >> 4) * 8;
    const int b_c8 = (lane >> 3) & 1;

    // Load Q (Qh then Ql): 2048 16B chunks
#pragma unroll
    for (int i = 0; i < 8; i++) {
        int g = i * 256 + tid;
        int row = (g >> 3) & 127, c = g & 7;
        const __nv_bfloat16* src = ((i >> 2) ? Ql : Qh) +
            ((size_t)bh * LL + q0 + row) * DD + (c << 3);
        uint32_t dst = sb + (i >> 2) * 16384 + row * 128 + ((c ^ (row & 7)) << 4);
        CP_ASYNC16(dst, src);
    }
    // Stage 0 (Kh, Kl, Vh, Vl): 4096 chunks
#pragma unroll
    for (int i = 0; i < 16; i++) {
        int g = i * 256 + tid;
        int which = g >> 10, local = g & 1023;
        int row = local >> 3, c = local & 7;
        const __nv_bfloat16* base =
            (which == 0) ? Kh : (which == 1) ? Kl : (which == 2) ? Vh : Vl;
        const __nv_bfloat16* src = base + ((size_t)bh * SS + row) * DD + (c << 3);
        uint32_t dst = sb + ASTG(0) + which * 16384 + row * 128 + ((c ^ (row & 7)) << 4);
        CP_ASYNC16(dst, src);
    }
    CP_COMMIT();

    float accO[2][8][4];
#pragma unroll
    for (int i = 0; i < 2; i++)
#pragma unroll
        for (int j = 0; j < 8; j++)
#pragma unroll
            for (int k = 0; k < 4; k++) accO[i][j][k] = 0.f;
    float psum[4] = {0.f, 0.f, 0.f, 0.f};

    for (int it = 0; it < 16; ++it) {
        const int s0 = it * 128, buf = it & 1;
        if (it + 1 < 16) {
            const int nbuf = (it + 1) & 1, ns0 = (it + 1) * 128;
#pragma unroll
            for (int i = 0; i < 16; i++) {
                int g = i * 256 + tid;
                int which = g >> 10, local = g & 1023;
                int row = local >> 3, c = local & 7;
                const __nv_bfloat16* base =
                    (which == 0) ? Kh : (which == 1) ? Kl : (which == 2) ? Vh : Vl;
                const __nv_bfloat16* src = base +
                    ((size_t)bh * SS + ns0 + row) * DD + (c << 3);
                uint32_t dst = sb + ASTG(nbuf) + which * 16384 + row * 128 +
                               ((c ^ (row & 7)) << 4);
                CP_ASYNC16(dst, src);
            }
        }
        CP_COMMIT();
        CP_WAIT1();
        __syncthreads();

        // ---- S = Q K^T (3-term split) ----
        float accS[2][8][4];
#pragma unroll
        for (int i = 0; i < 2; i++)
#pragma unroll
            for (int j = 0; j < 8; j++)
#pragma unroll
                for (int k = 0; k < 4; k++) accS[i][j][k] = 0.f;

        const uint32_t KB = sb + ASTG(buf);
#pragma unroll
        for (int kk = 0; kk < 12; kk++) {
            const int term = kk >> 2, kc = (kk & 3) * 16;
            const uint32_t Ab = sb + (term == 1 ? 16384 : 0);
            const uint32_t Bb = KB + (term == 2 ? 16384 : 0);
            uint32_t a[2][4];
#pragma unroll
            for (int mt = 0; mt < 2; mt++) {
                int row = wm * 32 + mt * 16 + a_r;
                int col = kc + 8 * a_c8;
                ldmatrix4(a[mt], Ab + row * 128 + (((col >> 3) ^ (row & 7)) << 4));
            }
            uint32_t b[4][4];
#pragma unroll
            for (int g = 0; g < 4; g++) {
                int row = wn * 64 + g * 16 + b_r;
                int col = kc + 8 * b_c8;
                ldmatrix4(b[g], Bb + row * 128 + (((col >> 3) ^ (row & 7)) << 4));
            }
#pragma unroll
            for (int mt = 0; mt < 2; mt++)
#pragma unroll
                for (int nt = 0; nt < 8; nt++)
                    mma16816(accS[mt][nt], a[mt],
                             b[nt >> 1][(nt & 1) * 2], b[nt >> 1][(nt & 1) * 2 + 1]);
        }

        // ---- logits + exp + PV (3-term) per 16-wide k-slice ----
        const uint32_t VB  = KB + 32768;
        const uint32_t VLB = KB + 49152;
#pragma unroll
        for (int ks = 0; ks < 4; ks++) {
            uint32_t pA[2][4], pAl[2][4];
#pragma unroll
            for (int mt = 0; mt < 2; mt++) {
#pragma unroll
                for (int sub = 0; sub < 2; sub++) {
                    const int nt = 2 * ks + sub;
                    const int row0 = q0 + wm * 32 + mt * 16 + (lane >> 2);
                    const int col = s0 + wn * 64 + nt * 8 + 2 * (lane & 3);
                    uchar2 kv2 = *(const uchar2*)&kpm[(size_t)nb * SS + col];
#pragma unroll
                    for (int half = 0; half < 2; half++) {
                        const int row = row0 + half * 8;
                        size_t base = ((size_t)bh * LL + row) * SS + col;
                        float2 pv = *(const float2*)&prev[base];
                        uchar2 av2 = *(const uchar2*)&am[(size_t)row * SS + col];
                        float c0 = accS[mt][nt][half * 2];
                        float c1 = accS[mt][nt][half * 2 + 1];
                        float lg0 = (av2.x | kv2.x) ? -INFINITY : fmaf(c0, 0.125f, pv.x);
                        float lg1 = (av2.y | kv2.y) ? -INFINITY : fmaf(c1, 0.125f, pv.y);
                        *(float2*)&out_logits[base] = make_float2(lg0, lg1);
                        float p0 = __expf(lg0), p1 = __expf(lg1);
                        psum[mt * 2 + half] += p0 + p1;
                        uint32_t ph = pk_bf16x2(p0, p1);
                        float r0 = p0 - __uint_as_float(ph << 16);
                        float r1 = p1 - __uint_as_float(ph & 0xffff0000u);
                        pA[mt][sub * 2 + half]  = ph;
                        pAl[mt][sub * 2 + half] = pk_bf16x2(r0, r1);
                    }
                }
            }
            uint32_t vb[4][4], vbl[4][4];
#pragma unroll
            for (int dg = 0; dg < 4; dg++) {
                int row = wn * 64 + ks * 16 + a_r;
                int chunk = dg * 2 + (lane >> 4);
                ldmatrix4t(vb[dg],  VB  + row * 128 + ((chunk ^ (row & 7)) << 4));
                ldmatrix4t(vbl[dg], VLB + row * 128 + ((chunk ^ (row & 7)) << 4));
            }
#pragma unroll
            for (int mt = 0; mt < 2; mt++)
#pragma unroll
                for (int dn = 0; dn < 8; dn++) {
                    uint32_t bh0 = vb[dn >> 1][(dn & 1) * 2];
                    uint32_t bh1 = vb[dn >> 1][(dn & 1) * 2 + 1];
                    mma16816(accO[mt][dn], pA[mt], bh0, bh1);
                    mma16816(accO[mt][dn], pAl[mt], bh0, bh1);
                    mma16816(accO[mt][dn], pA[mt],
                             vbl[dn >> 1][(dn & 1) * 2], vbl[dn >> 1][(dn & 1) * 2 + 1]);
                }
        }
        __syncthreads();
    }

    // ---- epilogue: row-sum reduce, cross-warp O sum, normalize, split-write ----
    float* ls = (float*)(sm + ALS);
#pragma unroll
    for (int idx = 0; idx < 4; idx++) {
        float v = psum[idx];
        v += __shfl_xor_sync(0xffffffffu, v, 1);
        v += __shfl_xor_sync(0xffffffffu, v, 2);
        int row = wm * 32 + (idx >> 1) * 16 + (idx & 1) * 8 + (lane >> 2);
        if ((lane & 3) == 0) ls[wn * 128 + row] = v;
    }
    __syncthreads();
    float* ob = (float*)(sm + 32768);      // reuse stage0 (32KB)
    if (wn == 1) {
#pragma unroll
        for (int mt = 0; mt < 2; mt++)
#pragma unroll
            for (int dn = 0; dn < 8; dn++) {
                int rl = wm * 32 + mt * 16 + (lane >> 2);
                int col = dn * 8 + 2 * (lane & 3);
                *(float2*)&ob[rl * 64 + col] =
                    make_float2(accO[mt][dn][0], accO[mt][dn][1]);
                *(float2*)&ob[(rl + 8) * 64 + col] =
                    make_float2(accO[mt][dn][2], accO[mt][dn][3]);
            }
    }
    __syncthreads();
    if (wn == 0) {
#pragma unroll
        for (int mt = 0; mt < 2; mt++)
#pragma unroll
            for (int dn = 0; dn < 8; dn++)
#pragma unroll
                for (int half = 0; half < 2; half++) {
                    int rl = wm * 32 + mt * 16 + (lane >> 2) + half * 8;
                    int col = dn * 8 + 2 * (lane & 3);
                    float2 o2 = *(float2*)&ob[rl * 64 + col];
                    float inv = 1.f / (ls[rl] + ls[128 + rl]);
                    float o0 = (accO[mt][dn][half * 2] + o2.x) * inv;
                    float o1 = (accO[mt][dn][half * 2 + 1] + o2.y) * inv;
                    size_t r = (size_t)(q0 + rl) * NB + nb;
                    size_t cg = hh * 64 + col;
                    uint32_t hv = pk_bf16x2(o0, o1);
                    float r0 = o0 - __uint_as_float(hv << 16);
                    float r1 = o1 - __uint_as_float(hv & 0xffff0000u);
                    uint32_t lv = pk_bf16x2(r0, r1);
                    *(uint32_t*)&oh[r * EE + cg] = hv;
                    *(uint32_t*)&ol[r * EE + cg] = lv;
                }
    }
}

// ---------------------------------------------------------------------------
extern "C" void kernel_launch(void* const* d_in, const int* in_sizes, int n_in,
                              void* d_out, int out_size)
{
    const float* query = (const float*)d_in[0];
    const float* key   = (const float*)d_in[1];
    const float* value = (const float*)d_in[2];
    const float* prev  = (const float*)d_in[3];
    const unsigned char* kpm = (const unsigned char*)d_in[4];
    const unsigned char* am  = (const unsigned char*)d_in[5];
    const float* Wq = (const float*)d_in[6];
    const float* Wk = (const float*)d_in[7];
    const float* Wv = (const float*)d_in[8];
    const float* Wo = (const float*)d_in[9];

    float* out = (float*)d_out;
    float* out_logits = out + (size_t)LL * NB * EE;

    __nv_bfloat16 *qh, *ql, *kh, *kl, *vh, *vl;
    __nv_bfloat16 *a3h, *a3l, *w3h, *w3l;
    cudaGetSymbolAddress((void**)&qh, g_qh);
    cudaGetSymbolAddress((void**)&ql, g_ql);
    cudaGetSymbolAddress((void**)&kh, g_kh);
    cudaGetSymbolAddress((void**)&kl, g_kl);
    cudaGetSymbolAddress((void**)&vh, g_vh);
    cudaGetSymbolAddress((void**)&vl, g_vl);
    cudaGetSymbolAddress((void**)&a3h, g_a3h);
    cudaGetSymbolAddress((void**)&a3l, g_a3l);
    cudaGetSymbolAddress((void**)&w3h, g_w3h);
    cudaGetSymbolAddress((void**)&w3l, g_w3l);

    const size_t ASZ = (size_t)MROWS * EE;
    const size_t WSZ = (size_t)EE * EE;

    cudaFuncSetAttribute(gemm_mma_bf16x3,
                         cudaFuncAttributeMaxDynamicSharedMemorySize, GSM_TOTAL);
    cudaFuncSetAttribute(attn_mma,
                         cudaFuncAttributeMaxDynamicSharedMemorySize, ASM_TOTAL);

    const int nsplit4 = MROWS * EE / 4;

    // 1) Transpose+split all 4 weight matrices (z = 4)
    WArgs wa;
    wa.W[0] = Wq; wa.W[1] = Wk; wa.W[2] = Wv; wa.W[3] = Wo;
    for (int z = 0; z < 4; z++) { wa.th[z] = w3h + z * WSZ; wa.tl[z] = w3l + z * WSZ; }
    wtrans_split<<<dim3(EE / 32, EE / 32, 4), 256>>>(wa);

    // 2) Split all 3 inputs (z = 3)
    SplitArgs sa;
    sa.x[0] = query; sa.x[1] = key; sa.x[2] = value;
    for (int z = 0; z < 3; z++) { sa.h[z] = a3h + z * ASZ; sa.l[z] = a3l + z * ASZ; }
    split_kernel<<<dim3((nsplit4 + 255) / 256, 1, 3), 256>>>(sa, nsplit4);

    // 3) Q/K/V projections in one launch (z = 3), bf16 hi/lo head-major out
    GemmArgs3 g3;
    __nv_bfloat16* dh[3] = {qh, kh, vh};
    __nv_bfloat16* dl[3] = {ql, kl, vl};
    for (int z = 0; z < 3; z++) {
        g3.g[z].ah = a3h + z * ASZ;  g3.g[z].al = a3l + z * ASZ;
        g3.g[z].bth = w3h + z * WSZ; g3.g[z].btl = w3l + z * WSZ;
        g3.g[z].dsth = dh[z];        g3.g[z].dstl = dl[z];
    }
    gemm_mma_bf16x3<<<dim3(EE / 128, MROWS / 128, 3), 256, GSM_TOTAL>>>(g3, nullptr, 1);

    // 4) Attention (writes logits + attn-out split into a3h[0]/a3l[0])
    attn_mma<<<dim3(LL / 128, BH), 256, ASM_TOTAL>>>(qh, ql, kh, kl, vh, vl,
                                                     prev, am, kpm,
                                                     out_logits, a3h, a3l);

    // 5) Output projection (fp32 row-major)
    GemmArgs3 go3;
    go3.g[0].ah = a3h;               go3.g[0].al = a3l;
    go3.g[0].bth = w3h + 3 * WSZ;    go3.g[0].btl = w3l + 3 * WSZ;
    go3.g[0].dsth = nullptr;         go3.g[0].dstl = nullptr;
    go3.g[1] = go3.g[0]; go3.g[2] = go3.g[0];
    gemm_mma_bf16x3<<<dim3(EE / 128, MROWS / 128, 1), 256, GSM_TOTAL>>>(go3, out, 0);
}